// round 14
// baseline (speedup 1.0000x reference)
#include <cuda_runtime.h>
#include <float.h>
#include <stdint.h>

#define MAXN 32768
#define MAXG 2048

// Scratch (no allocations allowed -> __device__ globals)
__device__ float g_h[MAXN * 64];     // node embeddings
__device__ float g_hw[MAXN * 64];    // h @ weight      (per node, exact fp32)
__device__ float g_hv[MAXN * 64];    // h @ V1[0:64]    (per node, exact fp32)
__device__ float g_t[MAXG * 64];     // per (graph, feature): max + log(sum exp)
__device__ int   g_seg[MAXG + 1];    // segment starts in sorted batch_hyper

static __device__ __forceinline__ float tf32r(float x) {
    uint32_t r; asm("cvt.rna.tf32.f32 %0, %1;" : "=r"(r) : "f"(x));
    return __uint_as_float(r);
}
static __device__ __forceinline__ void mma8(float c[4], uint32_t a0, uint32_t a1,
                                            uint32_t a2, uint32_t a3,
                                            uint32_t b0, uint32_t b1) {
    asm volatile("mma.sync.aligned.m16n8k8.row.col.f32.tf32.tf32.f32 "
                 "{%0,%1,%2,%3}, {%4,%5,%6,%7}, {%8,%9}, {%0,%1,%2,%3};"
                 : "+f"(c[0]), "+f"(c[1]), "+f"(c[2]), "+f"(c[3])
                 : "r"(a0), "r"(a1), "r"(a2), "r"(a3), "r"(b0), "r"(b1));
}
static __device__ __forceinline__ void gbar(int id) {
    asm volatile("bar.sync %0, %1;" :: "r"(id), "r"(128) : "memory");
}

// ---------------------------------------------------------------------------
// Kernel 1: node MLP
// ---------------------------------------------------------------------------
__global__ __launch_bounds__(128)
void k_node_mlp(const float* __restrict__ x, const float* __restrict__ u,
                const int* __restrict__ batch, int N,
                const float* __restrict__ W1, const float* __restrict__ b1,
                const float* __restrict__ W2, const float* __restrict__ b2,
                const float* __restrict__ W3, const float* __restrict__ b3)
{
    __shared__ float sW1[640], sW2t[4096], sW3[4096], sb1[64], sb2[64], sb3[64];
    int tid = threadIdx.x;
    for (int i = tid; i < 640; i += 128) sW1[i] = W1[i];
    for (int i = tid; i < 4096; i += 128) {
        int m = i >> 6, k = i & 63;
        sW2t[k * 64 + m] = W2[i];
        sW3[i] = W3[i];
    }
    if (tid < 64) { sb1[tid] = b1[tid]; sb2[tid] = b2[tid]; sb3[tid] = b3[tid]; }
    __syncthreads();

    int n = blockIdx.x * 128 + tid;
    if (n >= N) return;

    float in[10];
#pragma unroll
    for (int k = 0; k < 6; k++) in[k] = x[n * 6 + k];
    int g = batch[n];
#pragma unroll
    for (int k = 0; k < 4; k++) in[6 + k] = u[g * 4 + k];

    float h1[64];
#pragma unroll
    for (int j = 0; j < 64; j++) h1[j] = sb1[j];
#pragma unroll
    for (int k = 0; k < 10; k++) {
        float v = in[k];
#pragma unroll
        for (int j = 0; j < 64; j += 4) {
            float4 w = *(const float4*)&sW1[k * 64 + j];
            h1[j]   = fmaf(v, w.x, h1[j]);   h1[j+1] = fmaf(v, w.y, h1[j+1]);
            h1[j+2] = fmaf(v, w.z, h1[j+2]); h1[j+3] = fmaf(v, w.w, h1[j+3]);
        }
    }
#pragma unroll
    for (int j = 0; j < 64; j++) h1[j] = fmaxf(h1[j], 0.f);

    float acc[64];
#pragma unroll
    for (int j = 0; j < 64; j++) acc[j] = sb3[j];
    for (int k = 0; k < 64; k++) {
        float hv0 = sb2[k], hv1 = 0.f, hv2 = 0.f, hv3 = 0.f;
#pragma unroll
        for (int m = 0; m < 64; m += 4) {
            float4 w = *(const float4*)&sW2t[k * 64 + m];
            hv0 = fmaf(h1[m],   w.x, hv0); hv1 = fmaf(h1[m+1], w.y, hv1);
            hv2 = fmaf(h1[m+2], w.z, hv2); hv3 = fmaf(h1[m+3], w.w, hv3);
        }
        float hv = fmaxf(hv0 + hv1 + hv2 + hv3, 0.f);
#pragma unroll
        for (int j = 0; j < 64; j += 4) {
            float4 w = *(const float4*)&sW3[k * 64 + j];
            acc[j]   = fmaf(hv, w.x, acc[j]);   acc[j+1] = fmaf(hv, w.y, acc[j+1]);
            acc[j+2] = fmaf(hv, w.z, acc[j+2]); acc[j+3] = fmaf(hv, w.w, acc[j+3]);
        }
    }
#pragma unroll
    for (int j = 0; j < 64; j += 4)
        *(float4*)&g_h[n * 64 + j] = make_float4(acc[j], acc[j+1], acc[j+2], acc[j+3]);
}

// ---------------------------------------------------------------------------
// Kernel 1b: per-node precompute  g_hw = h @ Wt,  g_hv = h @ V1[0:64]
// ---------------------------------------------------------------------------
__global__ __launch_bounds__(128)
void k_node_post(int N, const float* __restrict__ Wt, const float* __restrict__ V1)
{
    __shared__ float sW[64 * 68];
    const float* src = (blockIdx.y == 0) ? Wt : V1;    // V1 rows 0..63 = top half
    float* dst = (blockIdx.y == 0) ? g_hw : g_hv;
    int tid = threadIdx.x;
    for (int i = tid; i < 4096; i += 128) {
        int k = i >> 6, j = i & 63;
        sW[k * 68 + j] = src[i];
    }
    __syncthreads();

    int n = blockIdx.x * 128 + tid;
    if (n >= N) return;

    const float* hrow = &g_h[n * 64];
    float acc[64];
#pragma unroll
    for (int j = 0; j < 64; j++) acc[j] = 0.f;
#pragma unroll 4
    for (int k = 0; k < 64; k++) {
        float hk = hrow[k];
#pragma unroll
        for (int j = 0; j < 64; j += 4) {
            float4 w = *(const float4*)&sW[k * 68 + j];
            acc[j]   = fmaf(hk, w.x, acc[j]);   acc[j+1] = fmaf(hk, w.y, acc[j+1]);
            acc[j+2] = fmaf(hk, w.z, acc[j+2]); acc[j+3] = fmaf(hk, w.w, acc[j+3]);
        }
    }
#pragma unroll
    for (int j = 0; j < 64; j += 4)
        *(float4*)&dst[n * 64 + j] = make_float4(acc[j], acc[j+1], acc[j+2], acc[j+3]);
}

// ---------------------------------------------------------------------------
// Kernel 2: segment starts from sorted batch_hyper
// ---------------------------------------------------------------------------
__global__ void k_seg(const int* __restrict__ bh, int E, int G)
{
    int e = blockIdx.x * blockDim.x + threadIdx.x;
    if (e >= E) return;
    int cur = bh[e];
    if (e == 0) { for (int g = 0; g <= cur; g++) g_seg[g] = 0; }
    else { int prev = bh[e - 1]; for (int g = prev + 1; g <= cur; g++) g_seg[g] = e; }
    if (e == E - 1) { for (int g = cur + 1; g <= G; g++) g_seg[g] = E; }
}

// ---------------------------------------------------------------------------
// Kernel 3: per-(graph, feature) softmax stats: t = max + log(sum exp)
// ---------------------------------------------------------------------------
__global__ __launch_bounds__(256)
void k_stats(const int* __restrict__ hei, int E, int R)
{
    int g = blockIdx.x;
    int s0 = g_seg[g], s1 = g_seg[g + 1];
    int f = threadIdx.x & 63, sub = threadIdx.x >> 6;

    float m = -FLT_MAX, s = 0.f;
    for (int e = s0 + sub; e < s1; e += 4) {
        float xh = 0.f;
        for (int ri = 0; ri < R; ri++) {
            int idx = hei[ri * E + e];
            xh += g_h[idx * 64 + f];
        }
        if (xh > m) { s = s * __expf(m - xh) + 1.f; m = xh; }
        else        { s += __expf(xh - m); }
    }
    __shared__ float sm[4][64], ss[4][64];
    sm[sub][f] = m; ss[sub][f] = s;
    __syncthreads();
    if (sub == 0) {
        float M = sm[0][f];
#pragma unroll
        for (int k = 1; k < 4; k++) M = fmaxf(M, sm[k][f]);
        float S = 0.f;
#pragma unroll
        for (int k = 0; k < 4; k++) S += ss[k][f] * __expf(sm[k][f] - M);
        g_t[g * 64 + f] = M + __logf(S);
    }
}

// ---------------------------------------------------------------------------
// Kernel 4: persistent fused edge pipeline (linearity-refactored).
// ---------------------------------------------------------------------------
#define SA 68
#define O_V1PK 0            // 4096  (V1 bottom half, fragment-packed tf32)
#define O_V2PK 4096         // 4096
#define O_XH   8192         // 4 x 4352  (x_hat, later mid)
#define O_XV   25600        // 4 x 4352  (xv accumulator init)
#define O_V3   43008
#define O_C1   43072
#define O_C2   43136
#define O_G    43200        // 4 x 64 ints
#define SMEM_FLOATS 43456   // 173,824 B

__device__ __forceinline__ void pass64(const float* __restrict__ A,
                                       const float* __restrict__ Bpk,
                                       int wg, int lane, float acc[8][4])
{
    int kr = lane & 3, rg = lane >> 2;
    const float* ap0 = A + (wg * 16 + rg) * SA + kr;
#pragma unroll
    for (int s = 0; s < 8; s++) {
        float bq[16];
#pragma unroll
        for (int q = 0; q < 4; q++)
            *(float4*)&bq[q * 4] = *(const float4*)&Bpk[s * 512 + q * 128 + lane * 4];
        uint32_t a0 = __float_as_uint(ap0[s * 8]);
        uint32_t a1 = __float_as_uint(ap0[s * 8 + 8 * SA]);
        uint32_t a2 = __float_as_uint(ap0[s * 8 + 4]);
        uint32_t a3 = __float_as_uint(ap0[s * 8 + 8 * SA + 4]);
#pragma unroll
        for (int nt = 0; nt < 8; nt++)
            mma8(acc[nt], a0, a1, a2, a3,
                 __float_as_uint(bq[2 * nt]), __float_as_uint(bq[2 * nt + 1]));
    }
}

__device__ __forceinline__ void packW(float* __restrict__ dst,
                                      const float* __restrict__ src, int tid, int nthr)
{
    for (int i = tid; i < 4096; i += nthr) {
        int s = i >> 9, r = i & 511;
        int q = r >> 7, r2 = r & 127;
        int l = r2 >> 2, c = r2 & 3;
        int kk = s * 8 + (l & 3) + (c & 1) * 4;
        int nn = (q * 2 + (c >> 1)) * 8 + (l >> 2);
        dst[i] = tf32r(src[kk * 64 + nn]);
    }
}

__global__ __launch_bounds__(512, 1)
void k_fused_tc(const int* __restrict__ hei, const int* __restrict__ bh,
                int E, int R, int ntiles,
                const float* __restrict__ V1, const float* __restrict__ c1,
                const float* __restrict__ V2, const float* __restrict__ c2,
                const float* __restrict__ V3, const float* __restrict__ c3,
                float* __restrict__ out, int write_bh)
{
    extern __shared__ float smf[];
    float* sV3 = smf + O_V3;
    float* sc1 = smf + O_C1;
    float* sc2 = smf + O_C2;

    int tid = threadIdx.x, lane = tid & 31, wid = tid >> 5;
    int gi = wid >> 2;
    int wg = wid & 3;
    int kr = lane & 3, rg = lane >> 2;
    int bar = gi + 1;
    int gt = tid & 127;

    float* XH = smf + O_XH + gi * 4352;
    float* XV = smf + O_XV + gi * 4352;
    int*   sG = (int*)(smf + O_G) + gi * 64;

    packW(smf + O_V1PK, V1 + 64 * 64, tid, 512);
    packW(smf + O_V2PK, V2,           tid, 512);
    if (tid < 64) { sV3[tid] = V3[tid]; sc1[tid] = c1[tid]; sc2[tid] = c2[tid]; }
    float c3v = c3[0];
    __syncthreads();

    for (int tile = blockIdx.x * 4 + gi; tile < ntiles; tile += gridDim.x * 4) {
        int base = tile * 64;

        // ---- P1: gather + elementwise x_hat ----
        {
            int el = gt & 63, half = gt >> 6, f0 = half * 32;
            int e = base + el; if (e >= E) e = E - 1;
            int g = bh[e];
            if (half == 0) sG[el] = g;
            int i0 = hei[e], i1 = hei[E + e], i2 = hei[2 * E + e];

            float xh[32], xw[32];
            {
                const float4* p0 = (const float4*)&g_h[i0 * 64 + f0];
                const float4* p1 = (const float4*)&g_h[i1 * 64 + f0];
                const float4* p2 = (const float4*)&g_h[i2 * 64 + f0];
#pragma unroll
                for (int q = 0; q < 8; q++) {
                    float4 a = p0[q], b = p1[q], c = p2[q];
                    xh[q*4+0] = a.x + b.x + c.x; xh[q*4+1] = a.y + b.y + c.y;
                    xh[q*4+2] = a.z + b.z + c.z; xh[q*4+3] = a.w + b.w + c.w;
                }
            }
            {
                const float4* p0 = (const float4*)&g_hw[i0 * 64 + f0];
                const float4* p1 = (const float4*)&g_hw[i1 * 64 + f0];
                const float4* p2 = (const float4*)&g_hw[i2 * 64 + f0];
#pragma unroll
                for (int q = 0; q < 8; q++) {
                    float4 a = p0[q], b = p1[q], c = p2[q];
                    xw[q*4+0] = a.x + b.x + c.x; xw[q*4+1] = a.y + b.y + c.y;
                    xw[q*4+2] = a.z + b.z + c.z; xw[q*4+3] = a.w + b.w + c.w;
                }
            }
            const float* trow = &g_t[g * 64 + f0];
            float* xd = &XH[el * SA + f0];
#pragma unroll
            for (int q = 0; q < 8; q++) {
                float4 t4 = *(const float4*)&trow[q * 4];
                float4 r;
                r.x = tf32r(__expf(xh[q*4+0] - t4.x) * fmaxf(xw[q*4+0], 0.f));
                r.y = tf32r(__expf(xh[q*4+1] - t4.y) * fmaxf(xw[q*4+1], 0.f));
                r.z = tf32r(__expf(xh[q*4+2] - t4.z) * fmaxf(xw[q*4+2], 0.f));
                r.w = tf32r(__expf(xh[q*4+3] - t4.w) * fmaxf(xw[q*4+3], 0.f));
                *(float4*)&xd[q * 4] = r;
            }
            {
                const float4* p0 = (const float4*)&g_hv[i0 * 64 + f0];
                const float4* p1 = (const float4*)&g_hv[i1 * 64 + f0];
                const float4* p2 = (const float4*)&g_hv[i2 * 64 + f0];
                float* vd = &XV[el * SA + f0];
#pragma unroll
                for (int q = 0; q < 8; q++) {
                    float4 a = p0[q], b = p1[q], c = p2[q];
                    *(float4*)&vd[q * 4] = make_float4(a.x + b.x + c.x, a.y + b.y + c.y,
                                                       a.z + b.z + c.z, a.w + b.w + c.w);
                }
            }
        }
        gbar(bar);   // B1

        float acc[8][4];
        int r0 = (wg * 16 + rg) * SA, r1 = r0 + 8 * SA;

        // ---- P2: acc = xv; acc += x_hat @ V1bot ----
#pragma unroll
        for (int nt = 0; nt < 8; nt++) {
            int j = nt * 8 + 2 * kr;
            float2 v0 = *(float2*)&XV[r0 + j];
            float2 v1 = *(float2*)&XV[r1 + j];
            acc[nt][0] = v0.x; acc[nt][1] = v0.y;
            acc[nt][2] = v1.x; acc[nt][3] = v1.y;
        }
        pass64(XH, smf + O_V1PK, wg, lane, acc);
        gbar(bar);   // B2

        // epi2: mid = relu(acc + c1) -> XH
#pragma unroll
        for (int nt = 0; nt < 8; nt++) {
            int j = nt * 8 + 2 * kr;
            float b0 = sc1[j], b1 = sc1[j + 1];
            *(float2*)&XH[r0 + j] = make_float2(tf32r(fmaxf(acc[nt][0] + b0, 0.f)),
                                                tf32r(fmaxf(acc[nt][1] + b1, 0.f)));
            *(float2*)&XH[r1 + j] = make_float2(tf32r(fmaxf(acc[nt][2] + b0, 0.f)),
                                                tf32r(fmaxf(acc[nt][3] + b1, 0.f)));
        }
        gbar(bar);   // B3

        // ---- P3: mid @ V2; dot V3; sigmoid; store ----
#pragma unroll
        for (int nt = 0; nt < 8; nt++)
#pragma unroll
            for (int c = 0; c < 4; c++) acc[nt][c] = 0.f;
        pass64(XH, smf + O_V2PK, wg, lane, acc);

        float s0 = 0.f, s1 = 0.f;
#pragma unroll
        for (int nt = 0; nt < 8; nt++) {
            int j = nt * 8 + 2 * kr;
            float b0 = sc2[j], b1 = sc2[j + 1];
            float w0 = sV3[j], w1 = sV3[j + 1];
            s0 = fmaf(fmaxf(acc[nt][0] + b0, 0.f), w0, s0);
            s0 = fmaf(fmaxf(acc[nt][1] + b1, 0.f), w1, s0);
            s1 = fmaf(fmaxf(acc[nt][2] + b0, 0.f), w0, s1);
            s1 = fmaf(fmaxf(acc[nt][3] + b1, 0.f), w1, s1);
        }
        s0 += __shfl_xor_sync(0xFFFFFFFF, s0, 1);
        s0 += __shfl_xor_sync(0xFFFFFFFF, s0, 2);
        s1 += __shfl_xor_sync(0xFFFFFFFF, s1, 1);
        s1 += __shfl_xor_sync(0xFFFFFFFF, s1, 2);
        if (kr == 0) {
            int row0 = wg * 16 + rg, row1 = row0 + 8;
            int e0 = base + row0, e1 = base + row1;
            float o0 = 1.f / (1.f + __expf(-(s0 + c3v)));
            float o1 = 1.f / (1.f + __expf(-(s1 + c3v)));
            if (e0 < E) {
                out[e0] = o0;
                if (write_bh) out[E + e0] = (float)sG[row0];
            }
            if (e1 < E) {
                out[e1] = o1;
                if (write_bh) out[E + e1] = (float)sG[row1];
            }
        }
        gbar(bar);   // B4
    }
}

// ---------------------------------------------------------------------------
extern "C" void kernel_launch(void* const* d_in, const int* in_sizes, int n_in,
                              void* d_out, int out_size)
{
    const float* x     = (const float*)d_in[0];
    const float* u     = (const float*)d_in[1];
    const int*   batch = (const int*)d_in[2];
    const int*   hei   = (const int*)d_in[3];
    const int*   bh    = (const int*)d_in[4];

    int N = in_sizes[2];
    int E = in_sizes[4];
    int G = in_sizes[1] / 4;
    int R = in_sizes[3] / E;

    int wb = 5;
    while (wb < n_in && in_sizes[wb] != 640) wb++;
    const float* W1 = (const float*)d_in[wb + 0];
    const float* b1 = (const float*)d_in[wb + 1];
    const float* W2 = (const float*)d_in[wb + 2];
    const float* b2 = (const float*)d_in[wb + 3];
    const float* W3 = (const float*)d_in[wb + 4];
    const float* b3 = (const float*)d_in[wb + 5];
    const float* Wt = (const float*)d_in[wb + 6];
    const float* V1 = (const float*)d_in[wb + 7];
    const float* c1 = (const float*)d_in[wb + 8];
    const float* V2 = (const float*)d_in[wb + 9];
    const float* c2 = (const float*)d_in[wb + 10];
    const float* V3 = (const float*)d_in[wb + 11];
    const float* c3 = (const float*)d_in[wb + 12];

    float* out = (float*)d_out;
    int write_bh = (out_size >= 2 * E) ? 1 : 0;

    k_node_mlp<<<(N + 127) / 128, 128>>>(x, u, batch, N, W1, b1, W2, b2, W3, b3);
    {
        dim3 gp((N + 127) / 128, 2);
        k_node_post<<<gp, 128>>>(N, Wt, V1);
    }
    k_seg<<<(E + 255) / 256, 256>>>(bh, E, G);
    k_stats<<<G, 256>>>(hei, E, R);

    int ntiles = (E + 63) / 64;
    int dev = 0, nsm = 148;
    cudaGetDevice(&dev);
    cudaDeviceGetAttribute(&nsm, cudaDevAttrMultiProcessorCount, dev);
    int grid = (ntiles + 3) / 4;
    if (grid > nsm) grid = nsm;
    if (grid < 1) grid = 1;

    size_t shbytes = (size_t)SMEM_FLOATS * sizeof(float);   // ~173.8 KB
    cudaFuncSetAttribute(k_fused_tc, cudaFuncAttributeMaxDynamicSharedMemorySize, (int)shbytes);
    k_fused_tc<<<grid, 512, shbytes>>>(hei, bh, E, R, ntiles, V1, c1, V2, c2,
                                       V3, c3, out, write_bh);
}

// round 17
// speedup vs baseline: 1.6168x; 1.6168x over previous
#include <cuda_runtime.h>
#include <float.h>
#include <stdint.h>

#define MAXN 32768
#define MAXG 2048

// Scratch (no allocations allowed -> __device__ globals)
__device__ float g_h[MAXN * 64];     // node embeddings (8 MB, L2-resident)
__device__ float g_t[MAXG * 64];     // per (graph, feature): log(sum exp)
__device__ int   g_seg[MAXG + 1];    // segment starts in sorted batch_hyper

static __device__ __forceinline__ float tf32r(float x) {
    uint32_t r; asm("cvt.rna.tf32.f32 %0, %1;" : "=r"(r) : "f"(x));
    return __uint_as_float(r);
}
static __device__ __forceinline__ void mma8(float c[4], uint32_t a0, uint32_t a1,
                                            uint32_t a2, uint32_t a3,
                                            uint32_t b0, uint32_t b1) {
    asm volatile("mma.sync.aligned.m16n8k8.row.col.f32.tf32.tf32.f32 "
                 "{%0,%1,%2,%3}, {%4,%5,%6,%7}, {%8,%9}, {%0,%1,%2,%3};"
                 : "+f"(c[0]), "+f"(c[1]), "+f"(c[2]), "+f"(c[3])
                 : "r"(a0), "r"(a1), "r"(a2), "r"(a3), "r"(b0), "r"(b1));
}
static __device__ __forceinline__ void gbar(int id) {
    asm volatile("bar.sync %0, %1;" :: "r"(id), "r"(128) : "memory");
}

// ---------------------------------------------------------------------------
// Kernel 1: node MLP
// ---------------------------------------------------------------------------
__global__ __launch_bounds__(128)
void k_node_mlp(const float* __restrict__ x, const float* __restrict__ u,
                const int* __restrict__ batch, int N,
                const float* __restrict__ W1, const float* __restrict__ b1,
                const float* __restrict__ W2, const float* __restrict__ b2,
                const float* __restrict__ W3, const float* __restrict__ b3)
{
    __shared__ float sW1[640], sW2t[4096], sW3[4096], sb1[64], sb2[64], sb3[64];
    int tid = threadIdx.x;
    for (int i = tid; i < 640; i += 128) sW1[i] = W1[i];
    for (int i = tid; i < 4096; i += 128) {
        int m = i >> 6, k = i & 63;
        sW2t[k * 64 + m] = W2[i];
        sW3[i] = W3[i];
    }
    if (tid < 64) { sb1[tid] = b1[tid]; sb2[tid] = b2[tid]; sb3[tid] = b3[tid]; }
    __syncthreads();

    int n = blockIdx.x * 128 + tid;
    if (n >= N) return;

    float in[10];
#pragma unroll
    for (int k = 0; k < 6; k++) in[k] = x[n * 6 + k];
    int g = batch[n];
#pragma unroll
    for (int k = 0; k < 4; k++) in[6 + k] = u[g * 4 + k];

    float h1[64];
#pragma unroll
    for (int j = 0; j < 64; j++) h1[j] = sb1[j];
#pragma unroll
    for (int k = 0; k < 10; k++) {
        float v = in[k];
#pragma unroll
        for (int j = 0; j < 64; j += 4) {
            float4 w = *(const float4*)&sW1[k * 64 + j];
            h1[j]   = fmaf(v, w.x, h1[j]);   h1[j+1] = fmaf(v, w.y, h1[j+1]);
            h1[j+2] = fmaf(v, w.z, h1[j+2]); h1[j+3] = fmaf(v, w.w, h1[j+3]);
        }
    }
#pragma unroll
    for (int j = 0; j < 64; j++) h1[j] = fmaxf(h1[j], 0.f);

    float acc[64];
#pragma unroll
    for (int j = 0; j < 64; j++) acc[j] = sb3[j];
    for (int k = 0; k < 64; k++) {
        float hv0 = sb2[k], hv1 = 0.f, hv2 = 0.f, hv3 = 0.f;
#pragma unroll
        for (int m = 0; m < 64; m += 4) {
            float4 w = *(const float4*)&sW2t[k * 64 + m];
            hv0 = fmaf(h1[m],   w.x, hv0); hv1 = fmaf(h1[m+1], w.y, hv1);
            hv2 = fmaf(h1[m+2], w.z, hv2); hv3 = fmaf(h1[m+3], w.w, hv3);
        }
        float hv = fmaxf(hv0 + hv1 + hv2 + hv3, 0.f);
#pragma unroll
        for (int j = 0; j < 64; j += 4) {
            float4 w = *(const float4*)&sW3[k * 64 + j];
            acc[j]   = fmaf(hv, w.x, acc[j]);   acc[j+1] = fmaf(hv, w.y, acc[j+1]);
            acc[j+2] = fmaf(hv, w.z, acc[j+2]); acc[j+3] = fmaf(hv, w.w, acc[j+3]);
        }
    }
#pragma unroll
    for (int j = 0; j < 64; j += 4)
        *(float4*)&g_h[n * 64 + j] = make_float4(acc[j], acc[j+1], acc[j+2], acc[j+3]);
}

// ---------------------------------------------------------------------------
// Kernel 2: segment starts from sorted batch_hyper
// ---------------------------------------------------------------------------
__global__ void k_seg(const int* __restrict__ bh, int E, int G)
{
    int e = blockIdx.x * blockDim.x + threadIdx.x;
    if (e >= E) return;
    int cur = bh[e];
    if (e == 0) { for (int g = 0; g <= cur; g++) g_seg[g] = 0; }
    else { int prev = bh[e - 1]; for (int g = prev + 1; g <= cur; g++) g_seg[g] = e; }
    if (e == E - 1) { for (int g = cur + 1; g <= G; g++) g_seg[g] = E; }
}

// ---------------------------------------------------------------------------
// Kernel 3: per-(graph, feature) softmax stats, no-max single pass:
//   t[g][f] = log( sum_e exp(xh[e][f]) )   (xh bounded, fp32 exp is safe)
// 256 threads: 16 feature-quads x 16 edge-subs, float4 gathers.
// ---------------------------------------------------------------------------
__global__ __launch_bounds__(256)
void k_stats(const int* __restrict__ hei, int E, int R)
{
    int g = blockIdx.x;
    int s0 = g_seg[g], s1 = g_seg[g + 1];
    int fq = threadIdx.x & 15;         // feature quad: feats fq*4 .. fq*4+3
    int sub = threadIdx.x >> 4;        // 0..15

    float4 s = make_float4(0.f, 0.f, 0.f, 0.f);
    for (int e = s0 + sub; e < s1; e += 16) {
        float4 a = make_float4(0.f, 0.f, 0.f, 0.f);
        for (int ri = 0; ri < R; ri++) {
            int idx = hei[ri * E + e];
            float4 v = *(const float4*)&g_h[idx * 64 + fq * 4];
            a.x += v.x; a.y += v.y; a.z += v.z; a.w += v.w;
        }
        s.x += __expf(a.x); s.y += __expf(a.y);
        s.z += __expf(a.z); s.w += __expf(a.w);
    }
    __shared__ float sm[16][64];
    *(float4*)&sm[sub][fq * 4] = s;
    __syncthreads();
    if (threadIdx.x < 64) {
        int f = threadIdx.x;
        float S = 0.f;
#pragma unroll
        for (int k = 0; k < 16; k++) S += sm[k][f];
        g_t[g * 64 + f] = __logf(S);   // coef = exp(xh - t)
    }
}

// ---------------------------------------------------------------------------
// Kernel 4: persistent fused edge pipeline, mma.sync tf32 (round-5 best).
// 256 threads = TWO independent 4-warp groups, each on its own 128-edge tile
// with its own named barrier + staging buffers (latency overlap).
// Weights pre-packed in B-fragment order (LDS.128 loads).
// ---------------------------------------------------------------------------
#define SA 68
// SMEM float offsets
#define O_WPK  0            // 4096
#define O_V1PK 4096         // 8192 (two 64-K halves)
#define O_V2PK 12288        // 4096
#define O_X    16384        // 2 x 8704
#define O_H    33792        // 2 x 8704
#define O_V3   51200
#define O_C1   51264
#define O_C2   51328
#define O_G    51392        // 2 x 128 ints
#define SMEM_FLOATS 51648   // 206,592 B

// One K=64 slab: A row-major [128][SA], Bpk fragment-packed. Warp covers
// rows mq*32..mq*32+31, all 64 cols. acc[2][8][4].
__device__ __forceinline__ void pass64(const float* __restrict__ A,
                                       const float* __restrict__ Bpk,
                                       int mq, int lane, float acc[2][8][4])
{
    int kr = lane & 3, rg = lane >> 2;
#pragma unroll
    for (int s = 0; s < 8; s++) {
        float bq[16];
#pragma unroll
        for (int q = 0; q < 4; q++)
            *(float4*)&bq[q * 4] = *(const float4*)&Bpk[s * 512 + q * 128 + lane * 4];
#pragma unroll
        for (int mt = 0; mt < 2; mt++) {
            const float* ap = A + (mq * 32 + mt * 16 + rg) * SA + kr + s * 8;
            uint32_t a0 = __float_as_uint(ap[0]);
            uint32_t a1 = __float_as_uint(ap[8 * SA]);
            uint32_t a2 = __float_as_uint(ap[4]);
            uint32_t a3 = __float_as_uint(ap[8 * SA + 4]);
#pragma unroll
            for (int nt = 0; nt < 8; nt++)
                mma8(acc[mt][nt], a0, a1, a2, a3,
                     __float_as_uint(bq[2 * nt]), __float_as_uint(bq[2 * nt + 1]));
        }
    }
}

// Pack a 64x64 (k x n, row-major) block into B-fragment order (tf32).
__device__ __forceinline__ void packW(float* __restrict__ dst,
                                      const float* __restrict__ src, int tid)
{
    for (int i = tid; i < 4096; i += 256) {
        int s = i >> 9, r = i & 511;
        int q = r >> 7, r2 = r & 127;
        int l = r2 >> 2, c = r2 & 3;
        int kk = s * 8 + (l & 3) + (c & 1) * 4;
        int nn = (q * 2 + (c >> 1)) * 8 + (l >> 2);
        dst[i] = tf32r(src[kk * 64 + nn]);
    }
}

__global__ __launch_bounds__(256, 1)
void k_fused_tc(const int* __restrict__ hei, const int* __restrict__ bh,
                int E, int R, int ntiles,
                const float* __restrict__ Wt,
                const float* __restrict__ V1, const float* __restrict__ c1,
                const float* __restrict__ V2, const float* __restrict__ c2,
                const float* __restrict__ V3, const float* __restrict__ c3,
                float* __restrict__ out, int write_bh)
{
    extern __shared__ float smf[];
    float* sV3 = smf + O_V3;
    float* sc1 = smf + O_C1;
    float* sc2 = smf + O_C2;

    int tid = threadIdx.x, lane = tid & 31, wid = tid >> 5;
    int gi = wid >> 2;                 // group 0 or 1
    int mq = wid & 3;                  // warp's m-quarter within group
    int kr = lane & 3, rg = lane >> 2;
    int bar = gi + 1;
    int gt = tid & 127;                // thread id within group

    float* X = smf + O_X + gi * 8704;
    float* H = smf + O_H + gi * 8704;
    int*   sG = (int*)(smf + O_G) + gi * 128;

    // ---- one-time weight packing ----
    packW(smf + O_WPK,         Wt,           tid);
    packW(smf + O_V1PK,        V1,           tid);
    packW(smf + O_V1PK + 4096, V1 + 64 * 64, tid);
    packW(smf + O_V2PK,        V2,           tid);
    if (tid < 64) { sV3[tid] = V3[tid]; sc1[tid] = c1[tid]; sc2[tid] = c2[tid]; }
    float c3v = c3[0];
    __syncthreads();

    for (int tile = blockIdx.x * 2 + gi; tile < ntiles; tile += gridDim.x * 2) {
        int base = tile * 128;

        // ---- gather: one edge per thread, 64 feats; stage t-row into H ----
        {
            int e = base + gt; if (e >= E) e = E - 1;
            int g = bh[e];
            sG[gt] = g;
            float xa[64];
            {
                const float4* hp = (const float4*)&g_h[hei[e] * 64];
#pragma unroll
                for (int q = 0; q < 16; q++) {
                    float4 v = hp[q];
                    xa[q*4+0] = v.x; xa[q*4+1] = v.y; xa[q*4+2] = v.z; xa[q*4+3] = v.w;
                }
            }
            for (int ri = 1; ri < R; ri++) {
                const float4* hp = (const float4*)&g_h[hei[ri * E + e] * 64];
#pragma unroll
                for (int q = 0; q < 16; q++) {
                    float4 v = hp[q];
                    xa[q*4+0] += v.x; xa[q*4+1] += v.y; xa[q*4+2] += v.z; xa[q*4+3] += v.w;
                }
            }
            float* xd = &X[gt * SA];
#pragma unroll
            for (int q = 0; q < 16; q++)
                *(float4*)&xd[q * 4] = make_float4(xa[q*4], xa[q*4+1], xa[q*4+2], xa[q*4+3]);
            const float4* tp = (const float4*)&g_t[g * 64];
            float* td = &H[gt * SA];
#pragma unroll
            for (int q = 0; q < 16; q++)
                *(float4*)&td[q * 4] = tp[q];
        }
        gbar(bar);

        float acc[2][8][4];

        // ---- GEMM 1: x_hyper @ weight ----
#pragma unroll
        for (int a = 0; a < 2; a++)
#pragma unroll
            for (int b = 0; b < 8; b++)
#pragma unroll
                for (int c = 0; c < 4; c++) acc[a][b][c] = 0.f;
        pass64(X, smf + O_WPK, mq, lane, acc);

        // epi1: H = relu(d) * exp(x - t)   (t pre-staged in H, same positions)
#pragma unroll
        for (int mt = 0; mt < 2; mt++) {
            int r0 = (mq * 32 + mt * 16 + rg) * SA;
            int r1 = r0 + 8 * SA;
#pragma unroll
            for (int nt = 0; nt < 8; nt++) {
                int j = nt * 8 + 2 * kr;
                float2 x0 = *(float2*)&X[r0 + j], t0 = *(float2*)&H[r0 + j];
                float2 x1 = *(float2*)&X[r1 + j], t1 = *(float2*)&H[r1 + j];
                float h00 = fmaxf(acc[mt][nt][0], 0.f) * __expf(x0.x - t0.x);
                float h01 = fmaxf(acc[mt][nt][1], 0.f) * __expf(x0.y - t0.y);
                float h10 = fmaxf(acc[mt][nt][2], 0.f) * __expf(x1.x - t1.x);
                float h11 = fmaxf(acc[mt][nt][3], 0.f) * __expf(x1.y - t1.y);
                *(float2*)&H[r0 + j] = make_float2(h00, h01);
                *(float2*)&H[r1 + j] = make_float2(h10, h11);
            }
        }
        gbar(bar);

        // ---- GEMM 2: [x || x_hat] @ V1  (K = 128) ----
#pragma unroll
        for (int a = 0; a < 2; a++)
#pragma unroll
            for (int b = 0; b < 8; b++)
#pragma unroll
                for (int c = 0; c < 4; c++) acc[a][b][c] = 0.f;
        pass64(X, smf + O_V1PK,        mq, lane, acc);
        pass64(H, smf + O_V1PK + 4096, mq, lane, acc);
        gbar(bar);   // all GEMM2 reads of X/H done

        // epi2: mid = relu(d + c1) -> H
#pragma unroll
        for (int mt = 0; mt < 2; mt++) {
            int r0 = (mq * 32 + mt * 16 + rg) * SA;
            int r1 = r0 + 8 * SA;
#pragma unroll
            for (int nt = 0; nt < 8; nt++) {
                int j = nt * 8 + 2 * kr;
                float b0 = sc1[j], b1 = sc1[j + 1];
                *(float2*)&H[r0 + j] = make_float2(fmaxf(acc[mt][nt][0] + b0, 0.f),
                                                   fmaxf(acc[mt][nt][1] + b1, 0.f));
                *(float2*)&H[r1 + j] = make_float2(fmaxf(acc[mt][nt][2] + b0, 0.f),
                                                   fmaxf(acc[mt][nt][3] + b1, 0.f));
            }
        }
        gbar(bar);

        // ---- GEMM 3: mid @ V2 ----
#pragma unroll
        for (int a = 0; a < 2; a++)
#pragma unroll
            for (int b = 0; b < 8; b++)
#pragma unroll
                for (int c = 0; c < 4; c++) acc[a][b][c] = 0.f;
        pass64(H, smf + O_V2PK, mq, lane, acc);

        // epi3: relu(+c2), dot V3 over this thread's 16 cols, reduce over kr
#pragma unroll
        for (int mt = 0; mt < 2; mt++) {
            float s0 = 0.f, s1 = 0.f;
#pragma unroll
            for (int nt = 0; nt < 8; nt++) {
                int j = nt * 8 + 2 * kr;
                float b0 = sc2[j], b1 = sc2[j + 1];
                float w0 = sV3[j], w1 = sV3[j + 1];
                s0 = fmaf(fmaxf(acc[mt][nt][0] + b0, 0.f), w0, s0);
                s0 = fmaf(fmaxf(acc[mt][nt][1] + b1, 0.f), w1, s0);
                s1 = fmaf(fmaxf(acc[mt][nt][2] + b0, 0.f), w0, s1);
                s1 = fmaf(fmaxf(acc[mt][nt][3] + b1, 0.f), w1, s1);
            }
            s0 += __shfl_xor_sync(0xFFFFFFFF, s0, 1);
            s0 += __shfl_xor_sync(0xFFFFFFFF, s0, 2);
            s1 += __shfl_xor_sync(0xFFFFFFFF, s1, 1);
            s1 += __shfl_xor_sync(0xFFFFFFFF, s1, 2);
            if (kr == 0) {
                int r0 = mq * 32 + mt * 16 + rg;
                int e0 = base + r0, e1 = e0 + 8;
                float o0 = 1.f / (1.f + __expf(-s0));
                float o1 = 1.f / (1.f + __expf(-s1));
                if (e0 < E) {
                    out[e0] = o0;
                    if (write_bh) out[E + e0] = (float)sG[r0];
                }
                if (e1 < E) {
                    out[e1] = o1;
                    if (write_bh) out[E + e1] = (float)sG[r0 + 8];
                }
            }
        }
        gbar(bar);   // protect X/H from next tile's gather
    }
}

// ---------------------------------------------------------------------------
extern "C" void kernel_launch(void* const* d_in, const int* in_sizes, int n_in,
                              void* d_out, int out_size)
{
    const float* x     = (const float*)d_in[0];
    const float* u     = (const float*)d_in[1];
    const int*   batch = (const int*)d_in[2];
    const int*   hei   = (const int*)d_in[3];
    const int*   bh    = (const int*)d_in[4];

    int N = in_sizes[2];
    int E = in_sizes[4];
    int G = in_sizes[1] / 4;
    int R = in_sizes[3] / E;

    int wb = 5;
    while (wb < n_in && in_sizes[wb] != 640) wb++;
    const float* W1 = (const float*)d_in[wb + 0];
    const float* b1 = (const float*)d_in[wb + 1];
    const float* W2 = (const float*)d_in[wb + 2];
    const float* b2 = (const float*)d_in[wb + 3];
    const float* W3 = (const float*)d_in[wb + 4];
    const float* b3 = (const float*)d_in[wb + 5];
    const float* Wt = (const float*)d_in[wb + 6];
    const float* V1 = (const float*)d_in[wb + 7];
    const float* c1 = (const float*)d_in[wb + 8];
    const float* V2 = (const float*)d_in[wb + 9];
    const float* c2 = (const float*)d_in[wb + 10];
    const float* V3 = (const float*)d_in[wb + 11];
    const float* c3 = (const float*)d_in[wb + 12];

    float* out = (float*)d_out;
    int write_bh = (out_size >= 2 * E) ? 1 : 0;

    k_node_mlp<<<(N + 127) / 128, 128>>>(x, u, batch, N, W1, b1, W2, b2, W3, b3);
    k_seg<<<(E + 255) / 256, 256>>>(bh, E, G);
    k_stats<<<G, 256>>>(hei, E, R);

    int ntiles = (E + 127) / 128;
    int dev = 0, nsm = 148;
    cudaGetDevice(&dev);
    cudaDeviceGetAttribute(&nsm, cudaDevAttrMultiProcessorCount, dev);
    int grid = (ntiles + 1) / 2;
    if (grid > nsm) grid = nsm;
    if (grid < 1) grid = 1;

    size_t shbytes = (size_t)SMEM_FLOATS * sizeof(float);   // ~206.6 KB
    cudaFuncSetAttribute(k_fused_tc, cudaFuncAttributeMaxDynamicSharedMemorySize, (int)shbytes);
    k_fused_tc<<<grid, 256, shbytes>>>(hei, bh, E, R, ntiles, Wt, V1, c1, V2, c2,
                                       V3, c3, out, write_bh);
}